// round 6
// baseline (speedup 1.0000x reference)
#include <cuda_runtime.h>

#define NN 30000
#define NE 480000
#define CH 64
#define NHEADS 4
#define KZ 256          // 64 channels x 4 heads
#define BNGRID 60

// ---------------- scratch (device globals; no allocations allowed) ----------------
__device__ __align__(16) float g_L[NN * 4];       // per-node head logits
__device__ __align__(16) float g_attn[NE * 4];    // per-edge softmaxed attention
__device__ __align__(16) float g_Z[NN * KZ];      // aggregated weighted features [node][k*4+m]
__device__ __align__(16) float g_H[NN * CH];      // relu(conv) output between layers
__device__ __align__(16) float g_Wp[KZ * CH];     // permuted weight for current layer
__device__ int   g_deg[NN];
__device__ int   g_rowptr[NN + 1];
__device__ int   g_wptr[NN];
__device__ int   g_perm[NE];
__device__ float g_bnp[BNGRID * CH];
__device__ float g_bnp2[BNGRID * CH];
__device__ float g_scale[CH];
__device__ float g_shift[CH];

// ---------------- CSR build ----------------
__global__ void k_zero_deg() {
    int i = blockIdx.x * blockDim.x + threadIdx.x;
    if (i < NN) g_deg[i] = 0;
}

__global__ void k_count(const int* __restrict__ dstE) {
    int e = blockIdx.x * blockDim.x + threadIdx.x;
    if (e < NE) atomicAdd(&g_deg[dstE[e]], 1);
}

// single-block exclusive scan over 30000 counts
__global__ void k_scan() {
    __shared__ int sh[1024];
    __shared__ int carry;
    int t = threadIdx.x;
    if (t == 0) carry = 0;
    __syncthreads();
    for (int base = 0; base < NN; base += 1024) {
        int i = base + t;
        int v = (i < NN) ? g_deg[i] : 0;
        sh[t] = v;
        __syncthreads();
        for (int off = 1; off < 1024; off <<= 1) {
            int add = (t >= off) ? sh[t - off] : 0;
            __syncthreads();
            sh[t] += add;
            __syncthreads();
        }
        int excl = carry + sh[t] - v;
        if (i < NN) { g_rowptr[i] = excl; g_wptr[i] = excl; }
        __syncthreads();
        if (t == 1023) carry = carry + sh[1023];
        __syncthreads();
    }
    if (t == 0) g_rowptr[NN] = carry;
}

__global__ void k_scatter(const int* __restrict__ dstE) {
    int e = blockIdx.x * blockDim.x + threadIdx.x;
    if (e < NE) {
        int d = dstE[e];
        int p = atomicAdd(&g_wptr[d], 1);
        g_perm[p] = e;
    }
}

// ---------------- per-node head logits: L[n][m] = sum_k xhat[n][k] * U[m][k] ----------------
// xhat = X*g_scale + g_shift if use_bn; X==nullptr -> g_H
__global__ void k_L(const float* __restrict__ X, const float* __restrict__ U, int use_bn) {
    int w = (blockIdx.x * blockDim.x + threadIdx.x) >> 5;
    int t = threadIdx.x & 31;
    if (w >= NN) return;
    const float* Xp = X ? X : g_H;
    int k0 = 2 * t;
    float sc0 = 1.f, sc1 = 1.f, sh0 = 0.f, sh1 = 0.f;
    if (use_bn) { sc0 = g_scale[k0]; sc1 = g_scale[k0 + 1]; sh0 = g_shift[k0]; sh1 = g_shift[k0 + 1]; }
    float2 xv = *(const float2*)(Xp + (size_t)w * CH + k0);
    float x0 = fmaf(xv.x, sc0, sh0);
    float x1 = fmaf(xv.y, sc1, sh1);
    float p0 = x0 * U[0 * CH + k0] + x1 * U[0 * CH + k0 + 1];
    float p1 = x0 * U[1 * CH + k0] + x1 * U[1 * CH + k0 + 1];
    float p2 = x0 * U[2 * CH + k0] + x1 * U[2 * CH + k0 + 1];
    float p3 = x0 * U[3 * CH + k0] + x1 * U[3 * CH + k0 + 1];
    #pragma unroll
    for (int off = 16; off; off >>= 1) {
        p0 += __shfl_xor_sync(0xFFFFFFFFu, p0, off);
        p1 += __shfl_xor_sync(0xFFFFFFFFu, p1, off);
        p2 += __shfl_xor_sync(0xFFFFFFFFu, p2, off);
        p3 += __shfl_xor_sync(0xFFFFFFFFu, p3, off);
    }
    if (t == 0) {
        *(float4*)(g_L + (size_t)w * 4) = make_float4(p0, p1, p2, p3);
    }
}

// ---------------- per-edge attention: softmax over 4 heads of (L[dst]-L[src]+c) ----------------
__global__ void k_attn(const int* __restrict__ srcE, const int* __restrict__ dstE,
                       const float* __restrict__ cc) {
    int e = blockIdx.x * blockDim.x + threadIdx.x;
    if (e >= NE) return;
    int s = srcE[e];
    int d = dstE[e];
    float4 ld = *(const float4*)(g_L + (size_t)d * 4);
    float4 ls = *(const float4*)(g_L + (size_t)s * 4);
    float l0 = ld.x - ls.x + cc[0];
    float l1 = ld.y - ls.y + cc[1];
    float l2 = ld.z - ls.z + cc[2];
    float l3 = ld.w - ls.w + cc[3];
    float mx = fmaxf(fmaxf(l0, l1), fmaxf(l2, l3));
    float e0 = __expf(l0 - mx), e1 = __expf(l1 - mx), e2 = __expf(l2 - mx), e3 = __expf(l3 - mx);
    float inv = __fdividef(1.f, e0 + e1 + e2 + e3);
    *(float4*)(g_attn + (size_t)e * 4) = make_float4(e0 * inv, e1 * inv, e2 * inv, e3 * inv);
}

// ---------------- warp-per-node aggregation into Z ----------------
// Z[v][k*4+m] = (1/cnt) * [ attn_self[m]*xhat[v][k] + sum_{e into v} attn[e][m]*xhat[src_e][k] ]
__global__ void k_edge(const float* __restrict__ X, const int* __restrict__ srcE,
                       const float* __restrict__ cc, int use_bn) {
    int w = (blockIdx.x * blockDim.x + threadIdx.x) >> 5;
    int t = threadIdx.x & 31;
    if (w >= NN) return;
    const float* Xp = X ? X : g_H;
    int lo = g_rowptr[w], hi = g_rowptr[w + 1];
    float inv = __fdividef(1.f, (float)(hi - lo + 1));
    int k0 = 2 * t;
    float sc0 = 1.f, sc1 = 1.f, sh0 = 0.f, sh1 = 0.f;
    if (use_bn) { sc0 = g_scale[k0]; sc1 = g_scale[k0 + 1]; sh0 = g_shift[k0]; sh1 = g_shift[k0 + 1]; }
    // self-loop attention = softmax(c)
    float c0 = cc[0], c1 = cc[1], c2 = cc[2], c3 = cc[3];
    float mx = fmaxf(fmaxf(c0, c1), fmaxf(c2, c3));
    float e0 = __expf(c0 - mx), e1 = __expf(c1 - mx), e2 = __expf(c2 - mx), e3 = __expf(c3 - mx);
    float si = __fdividef(1.f, e0 + e1 + e2 + e3);
    float2 xv = *(const float2*)(Xp + (size_t)w * CH + k0);
    float xv0 = fmaf(xv.x, sc0, sh0);
    float xv1 = fmaf(xv.y, sc1, sh1);
    float a00 = e0 * si * xv0, a10 = e1 * si * xv0, a20 = e2 * si * xv0, a30 = e3 * si * xv0;
    float a01 = e0 * si * xv1, a11 = e1 * si * xv1, a21 = e2 * si * xv1, a31 = e3 * si * xv1;
    for (int i = lo; i < hi; i++) {
        int eid = g_perm[i];
        float4 a = *(const float4*)(g_attn + (size_t)eid * 4);
        int s = srcE[eid];
        float2 xs = *(const float2*)(Xp + (size_t)s * CH + k0);
        float xs0 = fmaf(xs.x, sc0, sh0);
        float xs1 = fmaf(xs.y, sc1, sh1);
        a00 = fmaf(a.x, xs0, a00); a10 = fmaf(a.y, xs0, a10);
        a20 = fmaf(a.z, xs0, a20); a30 = fmaf(a.w, xs0, a30);
        a01 = fmaf(a.x, xs1, a01); a11 = fmaf(a.y, xs1, a11);
        a21 = fmaf(a.z, xs1, a21); a31 = fmaf(a.w, xs1, a31);
    }
    float4 r0 = make_float4(a00 * inv, a10 * inv, a20 * inv, a30 * inv);
    float4 r1 = make_float4(a01 * inv, a11 * inv, a21 * inv, a31 * inv);
    float* zr = g_Z + (size_t)w * KZ + k0 * 4;
    *(float4*)(zr)     = r0;
    *(float4*)(zr + 4) = r1;
}

// ---------------- permute W into g_Wp: Wp[c*4+m][o] = W[m*64+o][c] ----------------
__global__ void k_permW(const float* __restrict__ W) {
    int idx = blockIdx.x * blockDim.x + threadIdx.x;   // over KZ*CH = 16384
    if (idx >= KZ * CH) return;
    int r = idx >> 6;   // W row = m*64+o
    int c = idx & 63;   // channel
    int m = r >> 6;
    int o = r & 63;
    g_Wp[(c * 4 + m) * CH + o] = W[idx];
}

// ---------------- dense GEMM: out[v][o] = sum_kz Z[v][kz] * Wp[kz][o] + b[o] ----------------
// BM=128 nodes, N=64 full, K=256 in 4 chunks of 64. Xs transposed in static smem.
// W read straight from g_Wp (64 KB, L1-resident, broadcast across warps).
__global__ void __launch_bounds__(256) k_gemm(const float* __restrict__ b,
                                              float* __restrict__ extout, int relu) {
    __shared__ float Xs[64 * 132];
    int tid = threadIdx.x;
    int nb = blockIdx.x * 128;
    float* out = extout ? extout : g_H;

    float acc[8][4];
    #pragma unroll
    for (int i = 0; i < 8; i++)
        #pragma unroll
        for (int j = 0; j < 4; j++) acc[i][j] = 0.f;

    int tx = tid & 15;      // col group (4 cols)
    int ty = tid >> 4;      // node group (8 nodes)

    for (int kc = 0; kc < 4; kc++) {
        // stage 64 k-rows x 128 nodes of Z, transposed
        #pragma unroll
        for (int i = 0; i < 8; i++) {
            int f = i * 256 + tid;
            int nl = f >> 4;
            int kl = (f & 15) << 2;
            int node = nb + nl;
            float4 z = make_float4(0.f, 0.f, 0.f, 0.f);
            if (node < NN) z = *(const float4*)(g_Z + (size_t)node * KZ + kc * 64 + kl);
            Xs[(kl + 0) * 132 + nl] = z.x;
            Xs[(kl + 1) * 132 + nl] = z.y;
            Xs[(kl + 2) * 132 + nl] = z.z;
            Xs[(kl + 3) * 132 + nl] = z.w;
        }
        __syncthreads();
        #pragma unroll 8
        for (int kk = 0; kk < 64; kk++) {
            const float* xr = Xs + kk * 132 + ty * 8;
            float4 xa = *(const float4*)xr;
            float4 xb = *(const float4*)(xr + 4);
            float4 wv = *(const float4*)(g_Wp + (size_t)(kc * 64 + kk) * CH + tx * 4);
            float xv[8] = {xa.x, xa.y, xa.z, xa.w, xb.x, xb.y, xb.z, xb.w};
            #pragma unroll
            for (int i = 0; i < 8; i++) {
                acc[i][0] = fmaf(xv[i], wv.x, acc[i][0]);
                acc[i][1] = fmaf(xv[i], wv.y, acc[i][1]);
                acc[i][2] = fmaf(xv[i], wv.z, acc[i][2]);
                acc[i][3] = fmaf(xv[i], wv.w, acc[i][3]);
            }
        }
        __syncthreads();
    }

    float4 bv = *(const float4*)(b + tx * 4);
    #pragma unroll
    for (int i = 0; i < 8; i++) {
        int node = nb + ty * 8 + i;
        if (node < NN) {
            float4 r;
            r.x = acc[i][0] + bv.x;
            r.y = acc[i][1] + bv.y;
            r.z = acc[i][2] + bv.z;
            r.w = acc[i][3] + bv.w;
            if (relu) {
                r.x = fmaxf(r.x, 0.f); r.y = fmaxf(r.y, 0.f);
                r.z = fmaxf(r.z, 0.f); r.w = fmaxf(r.w, 0.f);
            }
            *(float4*)(out + (size_t)node * CH + tx * 4) = r;
        }
    }
}

// ---------------- batch-norm statistics (two-stage, deterministic) ----------------
__global__ void k_bnstat() {
    int ch = threadIdx.x & 63;
    int rg = threadIdx.x >> 6;   // 0..3
    float s = 0.f, s2 = 0.f;
    for (int v = blockIdx.x * 4 + rg; v < NN; v += BNGRID * 4) {
        float val = g_H[(size_t)v * CH + ch];
        s += val;
        s2 += val * val;
    }
    __shared__ float sh[4][64], sh2[4][64];
    sh[rg][ch] = s; sh2[rg][ch] = s2;
    __syncthreads();
    if (rg == 0) {
        s  = sh[0][ch]  + sh[1][ch]  + sh[2][ch]  + sh[3][ch];
        s2 = sh2[0][ch] + sh2[1][ch] + sh2[2][ch] + sh2[3][ch];
        g_bnp[blockIdx.x * 64 + ch]  = s;
        g_bnp2[blockIdx.x * 64 + ch] = s2;
    }
}

__global__ void k_bnfinal(const float* __restrict__ g, const float* __restrict__ bt) {
    int ch = threadIdx.x;
    if (ch >= CH) return;
    float s = 0.f, s2 = 0.f;
    for (int bidx = 0; bidx < BNGRID; bidx++) {
        s  += g_bnp[bidx * 64 + ch];
        s2 += g_bnp2[bidx * 64 + ch];
    }
    float mu = s / (float)NN;
    float var = s2 / (float)NN - mu * mu;
    float sc = g[ch] * rsqrtf(var + 1e-5f);
    g_scale[ch] = sc;
    g_shift[ch] = bt[ch] - mu * sc;
}

// ---------------- launch ----------------
extern "C" void kernel_launch(void* const* d_in, const int* in_sizes, int n_in,
                              void* d_out, int out_size) {
    const float* x    = (const float*)d_in[0];
    const int*   ei   = (const int*)d_in[1];      // edge_index: int32 (JAX x64 disabled)
    const float* W0   = (const float*)d_in[2];
    const float* U0   = (const float*)d_in[3];
    const float* c0   = (const float*)d_in[4];
    const float* b0   = (const float*)d_in[5];
    const float* g0   = (const float*)d_in[6];
    const float* bt0  = (const float*)d_in[7];
    const float* W1   = (const float*)d_in[8];
    const float* U1   = (const float*)d_in[9];
    const float* c1   = (const float*)d_in[10];
    const float* b1   = (const float*)d_in[11];
    const float* g1   = (const float*)d_in[12];
    const float* bt1  = (const float*)d_in[13];
    const float* W2   = (const float*)d_in[14];
    const float* U2   = (const float*)d_in[15];
    const float* c2   = (const float*)d_in[16];
    const float* b2   = (const float*)d_in[17];
    const int* srcE = ei;
    const int* dstE = ei + NE;
    float* out = (float*)d_out;

    const int GB_E = (NE + 255) / 256;      // 1875
    const int GB_N = (NN + 255) / 256;      // 118
    const int GB_W = NN / 8;                // 3750 (warp per node, exact)
    const int GB_G = (NN + 127) / 128;      // 235
    const int GB_P = (KZ * CH + 255) / 256; // 64

    // CSR build (graph fixed across layers)
    k_zero_deg<<<GB_N, 256>>>();
    k_count<<<GB_E, 256>>>(dstE);
    k_scan<<<1, 1024>>>();
    k_scatter<<<GB_E, 256>>>(dstE);

    // ---- layer 0 (input x, no BN folding) ----
    k_L<<<GB_W, 256>>>(x, U0, 0);
    k_attn<<<GB_E, 256>>>(srcE, dstE, c0);
    k_edge<<<GB_W, 256>>>(x, srcE, c0, 0);
    k_permW<<<GB_P, 256>>>(W0);
    k_gemm<<<GB_G, 256>>>(b0, nullptr, 1);    // -> g_H (relu'd)
    k_bnstat<<<BNGRID, 256>>>();
    k_bnfinal<<<1, 64>>>(g0, bt0);

    // ---- layer 1 (reads BN0(g_H) on the fly) ----
    k_L<<<GB_W, 256>>>(nullptr, U1, 1);
    k_attn<<<GB_E, 256>>>(srcE, dstE, c1);
    k_edge<<<GB_W, 256>>>(nullptr, srcE, c1, 1);
    k_permW<<<GB_P, 256>>>(W1);
    k_gemm<<<GB_G, 256>>>(b1, nullptr, 1);    // -> g_H (relu'd)
    k_bnstat<<<BNGRID, 256>>>();
    k_bnfinal<<<1, 64>>>(g1, bt1);

    // ---- layer 2 (reads BN1(g_H), no relu, writes d_out) ----
    k_L<<<GB_W, 256>>>(nullptr, U2, 1);
    k_attn<<<GB_E, 256>>>(srcE, dstE, c2);
    k_edge<<<GB_W, 256>>>(nullptr, srcE, c2, 1);
    k_permW<<<GB_P, 256>>>(W2);
    k_gemm<<<GB_G, 256>>>(b2, out, 0);

    (void)in_sizes; (void)n_in; (void)out_size;
}

// round 7
// speedup vs baseline: 1.2030x; 1.2030x over previous
#include <cuda_runtime.h>

#define NN 30000
#define NE 480000
#define CH 64
#define NHEADS 4
#define KZ 256          // 64 channels x 4 heads
#define BNGRID 60
#define SCAN_BLOCKS ((NN + 255) / 256)   // 118

typedef unsigned long long ull;

// ---------------- f32x2 helpers (sm_103a packed fp32 pipe) ----------------
__device__ __forceinline__ ull pk2(float lo, float hi) {
    ull r;
    asm("mov.b64 %0, {%1, %2};" : "=l"(r) : "f"(lo), "f"(hi));
    return r;
}
__device__ __forceinline__ void upk2(float& lo, float& hi, ull v) {
    asm("mov.b64 {%0, %1}, %2;" : "=f"(lo), "=f"(hi) : "l"(v));
}
__device__ __forceinline__ ull fma2(ull a, ull b, ull c) {
    ull d;
    asm("fma.rn.f32x2 %0, %1, %2, %3;" : "=l"(d) : "l"(a), "l"(b), "l"(c));
    return d;
}
__device__ __forceinline__ ull mul2(ull a, ull b) {
    ull d;
    asm("mul.rn.f32x2 %0, %1, %2;" : "=l"(d) : "l"(a), "l"(b));
    return d;
}

// ---------------- scratch (device globals; no allocations allowed) ----------------
__device__ __align__(16) float g_L[NN * 4];        // per-node head logits
__device__ __align__(16) float g_attnP[NE * 4];    // per-edge attention, CSR-permuted order
__device__ __align__(16) float g_Z[NN * KZ];       // aggregated weighted features [node][c*4+m]
__device__ __align__(16) float g_H[NN * CH];       // relu(conv) output between layers
__device__ __align__(16) float g_Wp[KZ * CH];      // permuted weight for current layer
__device__ int   g_deg[NN];
__device__ int   g_rowptr[NN + 1];
__device__ int   g_wptr[NN];
__device__ int   g_srcP[NE];                       // src node per CSR position
__device__ int   g_epos[NE];                       // CSR position per edge id
__device__ int   g_bsum[SCAN_BLOCKS];
__device__ int   g_boff[SCAN_BLOCKS];
__device__ float g_bnp[BNGRID * CH];
__device__ float g_bnp2[BNGRID * CH];
__device__ float g_scale[CH];
__device__ float g_shift[CH];

// ---------------- CSR build ----------------
__global__ void k_zero_deg() {
    int i = blockIdx.x * blockDim.x + threadIdx.x;
    if (i < NN) g_deg[i] = 0;
}

__global__ void k_count(const int* __restrict__ dstE) {
    int e = blockIdx.x * blockDim.x + threadIdx.x;
    if (e < NE) atomicAdd(&g_deg[dstE[e]], 1);
}

// block-level scan: each block scans 256 degrees, writes local exclusive + block sum
__global__ void k_scan1() {
    int b = blockIdx.x, t = threadIdx.x;
    int i = b * 256 + t;
    int v = (i < NN) ? g_deg[i] : 0;
    int lane = t & 31, wid = t >> 5;
    int x = v;
    #pragma unroll
    for (int off = 1; off < 32; off <<= 1) {
        int y = __shfl_up_sync(0xFFFFFFFFu, x, off);
        if (lane >= off) x += y;
    }
    __shared__ int wsum[8];
    if (lane == 31) wsum[wid] = x;
    __syncthreads();
    if (wid == 0) {
        int s = (lane < 8) ? wsum[lane] : 0;
        #pragma unroll
        for (int off = 1; off < 8; off <<= 1) {
            int y = __shfl_up_sync(0xFFFFFFFFu, s, off);
            if (lane >= off) s += y;
        }
        if (lane < 8) wsum[lane] = s;   // inclusive warp sums
    }
    __syncthreads();
    int base = (wid > 0) ? wsum[wid - 1] : 0;
    int excl = base + x - v;
    if (i < NN) g_rowptr[i] = excl;
    if (t == 255) g_bsum[b] = base + x;
}

// scan the 118 block sums (single small block)
__global__ void k_scan2() {
    int t = threadIdx.x;  // 128 threads
    int v = (t < SCAN_BLOCKS) ? g_bsum[t] : 0;
    int lane = t & 31, wid = t >> 5;
    int x = v;
    #pragma unroll
    for (int off = 1; off < 32; off <<= 1) {
        int y = __shfl_up_sync(0xFFFFFFFFu, x, off);
        if (lane >= off) x += y;
    }
    __shared__ int ws[4];
    if (lane == 31) ws[wid] = x;
    __syncthreads();
    if (t == 0) {
        int a = 0;
        #pragma unroll
        for (int wv = 0; wv < 4; wv++) { int tmp = ws[wv]; ws[wv] = a; a += tmp; }
    }
    __syncthreads();
    int excl = ws[wid] + x - v;
    if (t < SCAN_BLOCKS) g_boff[t] = excl;
    if (t == 0) g_rowptr[NN] = NE;
}

__global__ void k_scan3() {
    int b = blockIdx.x;
    int i = b * 256 + threadIdx.x;
    if (i < NN) {
        int r = g_rowptr[i] + g_boff[b];
        g_rowptr[i] = r;
        g_wptr[i] = r;
    }
}

__global__ void k_scatter(const int* __restrict__ srcE, const int* __restrict__ dstE) {
    int e = blockIdx.x * blockDim.x + threadIdx.x;
    if (e < NE) {
        int d = dstE[e];
        int p = atomicAdd(&g_wptr[d], 1);
        g_srcP[p] = srcE[e];
        g_epos[e] = p;
    }
}

// ---------------- per-node head logits: L[n][m] = sum_k xhat[n][k] * U[m][k] ----------------
__global__ void k_L(const float* __restrict__ X, const float* __restrict__ U, int use_bn) {
    int w = (blockIdx.x * blockDim.x + threadIdx.x) >> 5;
    int t = threadIdx.x & 31;
    if (w >= NN) return;
    const float* Xp = X ? X : g_H;
    int k0 = 2 * t;
    float sc0 = 1.f, sc1 = 1.f, sh0 = 0.f, sh1 = 0.f;
    if (use_bn) { sc0 = g_scale[k0]; sc1 = g_scale[k0 + 1]; sh0 = g_shift[k0]; sh1 = g_shift[k0 + 1]; }
    float2 xv = *(const float2*)(Xp + (size_t)w * CH + k0);
    float x0 = fmaf(xv.x, sc0, sh0);
    float x1 = fmaf(xv.y, sc1, sh1);
    float p0 = x0 * U[0 * CH + k0] + x1 * U[0 * CH + k0 + 1];
    float p1 = x0 * U[1 * CH + k0] + x1 * U[1 * CH + k0 + 1];
    float p2 = x0 * U[2 * CH + k0] + x1 * U[2 * CH + k0 + 1];
    float p3 = x0 * U[3 * CH + k0] + x1 * U[3 * CH + k0 + 1];
    #pragma unroll
    for (int off = 16; off; off >>= 1) {
        p0 += __shfl_xor_sync(0xFFFFFFFFu, p0, off);
        p1 += __shfl_xor_sync(0xFFFFFFFFu, p1, off);
        p2 += __shfl_xor_sync(0xFFFFFFFFu, p2, off);
        p3 += __shfl_xor_sync(0xFFFFFFFFu, p3, off);
    }
    if (t == 0) {
        *(float4*)(g_L + (size_t)w * 4) = make_float4(p0, p1, p2, p3);
    }
}

// ---------------- per-edge attention, written in CSR order ----------------
__global__ void k_attn(const int* __restrict__ srcE, const int* __restrict__ dstE,
                       const float* __restrict__ cc) {
    int e = blockIdx.x * blockDim.x + threadIdx.x;
    if (e >= NE) return;
    int s = srcE[e];
    int d = dstE[e];
    float4 ld = *(const float4*)(g_L + (size_t)d * 4);
    float4 ls = *(const float4*)(g_L + (size_t)s * 4);
    float l0 = ld.x - ls.x + cc[0];
    float l1 = ld.y - ls.y + cc[1];
    float l2 = ld.z - ls.z + cc[2];
    float l3 = ld.w - ls.w + cc[3];
    float mx = fmaxf(fmaxf(l0, l1), fmaxf(l2, l3));
    float e0 = __expf(l0 - mx), e1 = __expf(l1 - mx), e2 = __expf(l2 - mx), e3 = __expf(l3 - mx);
    float inv = __fdividef(1.f, e0 + e1 + e2 + e3);
    int p = g_epos[e];
    *(float4*)(g_attnP + (size_t)p * 4) = make_float4(e0 * inv, e1 * inv, e2 * inv, e3 * inv);
}

// ---------------- warp-per-node aggregation into Z (f32x2, 4x unrolled) ----------------
// Z[v][c*4+m] = (1/cnt) * [ attn_self[m]*xhat[v][c] + sum_e attn[e][m]*xhat[src_e][c] ]
__global__ void k_edge(const float* __restrict__ X, const float* __restrict__ cc, int use_bn) {
    int w = (blockIdx.x * blockDim.x + threadIdx.x) >> 5;
    int t = threadIdx.x & 31;
    if (w >= NN) return;
    const float* Xp = X ? X : g_H;
    int lo = g_rowptr[w], hi = g_rowptr[w + 1];
    float inv = __fdividef(1.f, (float)(hi - lo + 1));
    int k0 = 2 * t;
    float sc0 = 1.f, sc1 = 1.f, sh0 = 0.f, sh1 = 0.f;
    if (use_bn) { sc0 = g_scale[k0]; sc1 = g_scale[k0 + 1]; sh0 = g_shift[k0]; sh1 = g_shift[k0 + 1]; }

    // self-loop attention = softmax(c)
    float c0 = cc[0], c1 = cc[1], c2 = cc[2], c3 = cc[3];
    float mx = fmaxf(fmaxf(c0, c1), fmaxf(c2, c3));
    float e0 = __expf(c0 - mx), e1 = __expf(c1 - mx), e2 = __expf(c2 - mx), e3 = __expf(c3 - mx);
    float si = __fdividef(1.f, e0 + e1 + e2 + e3);
    ull W01 = pk2(e0 * si, e1 * si);
    ull W23 = pk2(e2 * si, e3 * si);

    float2 xv = *(const float2*)(Xp + (size_t)w * CH + k0);
    float xv0 = fmaf(xv.x, sc0, sh0);
    float xv1 = fmaf(xv.y, sc1, sh1);
    // acc[c][mpair]: channel c in {k0, k0+1}, head pair (0,1)/(2,3)
    ull acc00 = mul2(pk2(xv0, xv0), W01);
    ull acc01 = mul2(pk2(xv0, xv0), W23);
    ull acc10 = mul2(pk2(xv1, xv1), W01);
    ull acc11 = mul2(pk2(xv1, xv1), W23);

    int i = lo;
    for (; i + 4 <= hi; i += 4) {
        int s0 = g_srcP[i], s1 = g_srcP[i + 1], s2 = g_srcP[i + 2], s3 = g_srcP[i + 3];
        ulonglong2 A0 = *(const ulonglong2*)(g_attnP + (size_t)(i)     * 4);
        ulonglong2 A1 = *(const ulonglong2*)(g_attnP + (size_t)(i + 1) * 4);
        ulonglong2 A2 = *(const ulonglong2*)(g_attnP + (size_t)(i + 2) * 4);
        ulonglong2 A3 = *(const ulonglong2*)(g_attnP + (size_t)(i + 3) * 4);
        float2 x0 = *(const float2*)(Xp + (size_t)s0 * CH + k0);
        float2 x1 = *(const float2*)(Xp + (size_t)s1 * CH + k0);
        float2 x2 = *(const float2*)(Xp + (size_t)s2 * CH + k0);
        float2 x3 = *(const float2*)(Xp + (size_t)s3 * CH + k0);

        float a0 = fmaf(x0.x, sc0, sh0), b0 = fmaf(x0.y, sc1, sh1);
        ull pa0 = pk2(a0, a0), pb0 = pk2(b0, b0);
        acc00 = fma2(pa0, A0.x, acc00); acc01 = fma2(pa0, A0.y, acc01);
        acc10 = fma2(pb0, A0.x, acc10); acc11 = fma2(pb0, A0.y, acc11);

        float a1 = fmaf(x1.x, sc0, sh0), b1 = fmaf(x1.y, sc1, sh1);
        ull pa1 = pk2(a1, a1), pb1 = pk2(b1, b1);
        acc00 = fma2(pa1, A1.x, acc00); acc01 = fma2(pa1, A1.y, acc01);
        acc10 = fma2(pb1, A1.x, acc10); acc11 = fma2(pb1, A1.y, acc11);

        float a2 = fmaf(x2.x, sc0, sh0), b2 = fmaf(x2.y, sc1, sh1);
        ull pa2 = pk2(a2, a2), pb2 = pk2(b2, b2);
        acc00 = fma2(pa2, A2.x, acc00); acc01 = fma2(pa2, A2.y, acc01);
        acc10 = fma2(pb2, A2.x, acc10); acc11 = fma2(pb2, A2.y, acc11);

        float a3 = fmaf(x3.x, sc0, sh0), b3 = fmaf(x3.y, sc1, sh1);
        ull pa3 = pk2(a3, a3), pb3 = pk2(b3, b3);
        acc00 = fma2(pa3, A3.x, acc00); acc01 = fma2(pa3, A3.y, acc01);
        acc10 = fma2(pb3, A3.x, acc10); acc11 = fma2(pb3, A3.y, acc11);
    }
    for (; i < hi; i++) {
        int s = g_srcP[i];
        ulonglong2 A = *(const ulonglong2*)(g_attnP + (size_t)i * 4);
        float2 x = *(const float2*)(Xp + (size_t)s * CH + k0);
        float a = fmaf(x.x, sc0, sh0), b = fmaf(x.y, sc1, sh1);
        ull pa = pk2(a, a), pb = pk2(b, b);
        acc00 = fma2(pa, A.x, acc00); acc01 = fma2(pa, A.y, acc01);
        acc10 = fma2(pb, A.x, acc10); acc11 = fma2(pb, A.y, acc11);
    }

    ull iv = pk2(inv, inv);
    ulonglong2 r0, r1;
    r0.x = mul2(acc00, iv); r0.y = mul2(acc01, iv);
    r1.x = mul2(acc10, iv); r1.y = mul2(acc11, iv);
    float* zr = g_Z + (size_t)w * KZ + k0 * 4;
    *(ulonglong2*)(zr)     = r0;   // Z[c=k0][m0..3]
    *(ulonglong2*)(zr + 4) = r1;   // Z[c=k0+1][m0..3]
}

// ---------------- permute W into g_Wp: Wp[c*4+m][o] = W[m*64+o][c] ----------------
__global__ void k_permW(const float* __restrict__ W) {
    int idx = blockIdx.x * blockDim.x + threadIdx.x;   // over KZ*CH = 16384
    if (idx >= KZ * CH) return;
    int r = idx >> 6;   // W row = m*64+o
    int c = idx & 63;   // channel
    int m = r >> 6;
    int o = r & 63;
    g_Wp[(c * 4 + m) * CH + o] = W[idx];
}

// ---------------- dense GEMM with packed f32x2 FMAs ----------------
// out[v][o] = sum_kz Z[v][kz] * Wp[kz][o] + b[o].  BM=128, N=64, K=256 (4 chunks of 64).
__global__ void __launch_bounds__(256) k_gemm(const float* __restrict__ b,
                                              float* __restrict__ extout, int relu) {
    __shared__ __align__(16) float Xs[64 * 132];
    int tid = threadIdx.x;
    int nb = blockIdx.x * 128;
    float* out = extout ? extout : g_H;

    ull acc[4][4];  // [node pair][col]
    #pragma unroll
    for (int p = 0; p < 4; p++)
        #pragma unroll
        for (int j = 0; j < 4; j++) acc[p][j] = 0ull;

    int tx = tid & 15;      // col group (4 cols)
    int ty = tid >> 4;      // node group (8 nodes)

    for (int kc = 0; kc < 4; kc++) {
        // stage 64 k-rows x 128 nodes of Z, transposed
        #pragma unroll
        for (int i = 0; i < 8; i++) {
            int f = i * 256 + tid;
            int nl = f >> 4;
            int kl = (f & 15) << 2;
            int node = nb + nl;
            float4 z = make_float4(0.f, 0.f, 0.f, 0.f);
            if (node < NN) z = *(const float4*)(g_Z + (size_t)node * KZ + kc * 64 + kl);
            Xs[(kl + 0) * 132 + nl] = z.x;
            Xs[(kl + 1) * 132 + nl] = z.y;
            Xs[(kl + 2) * 132 + nl] = z.z;
            Xs[(kl + 3) * 132 + nl] = z.w;
        }
        __syncthreads();
        #pragma unroll 8
        for (int kk = 0; kk < 64; kk++) {
            const float* xr = Xs + kk * 132 + ty * 8;
            ulonglong2 xa = *(const ulonglong2*)xr;         // node pairs (0,1),(2,3)
            ulonglong2 xb = *(const ulonglong2*)(xr + 4);   // node pairs (4,5),(6,7)
            float4 wv = *(const float4*)(g_Wp + (size_t)(kc * 64 + kk) * CH + tx * 4);
            ull w0 = pk2(wv.x, wv.x), w1 = pk2(wv.y, wv.y);
            ull w2 = pk2(wv.z, wv.z), w3 = pk2(wv.w, wv.w);
            acc[0][0] = fma2(xa.x, w0, acc[0][0]); acc[0][1] = fma2(xa.x, w1, acc[0][1]);
            acc[0][2] = fma2(xa.x, w2, acc[0][2]); acc[0][3] = fma2(xa.x, w3, acc[0][3]);
            acc[1][0] = fma2(xa.y, w0, acc[1][0]); acc[1][1] = fma2(xa.y, w1, acc[1][1]);
            acc[1][2] = fma2(xa.y, w2, acc[1][2]); acc[1][3] = fma2(xa.y, w3, acc[1][3]);
            acc[2][0] = fma2(xb.x, w0, acc[2][0]); acc[2][1] = fma2(xb.x, w1, acc[2][1]);
            acc[2][2] = fma2(xb.x, w2, acc[2][2]); acc[2][3] = fma2(xb.x, w3, acc[2][3]);
            acc[3][0] = fma2(xb.y, w0, acc[3][0]); acc[3][1] = fma2(xb.y, w1, acc[3][1]);
            acc[3][2] = fma2(xb.y, w2, acc[3][2]); acc[3][3] = fma2(xb.y, w3, acc[3][3]);
        }
        __syncthreads();
    }

    float4 bv = *(const float4*)(b + tx * 4);
    #pragma unroll
    for (int p = 0; p < 4; p++) {
        float lo0, hi0, lo1, hi1, lo2, hi2, lo3, hi3;
        upk2(lo0, hi0, acc[p][0]);
        upk2(lo1, hi1, acc[p][1]);
        upk2(lo2, hi2, acc[p][2]);
        upk2(lo3, hi3, acc[p][3]);
        int n0 = nb + ty * 8 + 2 * p;
        if (n0 < NN) {
            float4 r = make_float4(lo0 + bv.x, lo1 + bv.y, lo2 + bv.z, lo3 + bv.w);
            if (relu) {
                r.x = fmaxf(r.x, 0.f); r.y = fmaxf(r.y, 0.f);
                r.z = fmaxf(r.z, 0.f); r.w = fmaxf(r.w, 0.f);
            }
            *(float4*)(out + (size_t)n0 * CH + tx * 4) = r;
        }
        int n1 = n0 + 1;
        if (n1 < NN) {
            float4 r = make_float4(hi0 + bv.x, hi1 + bv.y, hi2 + bv.z, hi3 + bv.w);
            if (relu) {
                r.x = fmaxf(r.x, 0.f); r.y = fmaxf(r.y, 0.f);
                r.z = fmaxf(r.z, 0.f); r.w = fmaxf(r.w, 0.f);
            }
            *(float4*)(out + (size_t)n1 * CH + tx * 4) = r;
        }
    }
}

// ---------------- batch-norm statistics (two-stage, deterministic) ----------------
__global__ void k_bnstat() {
    int ch = threadIdx.x & 63;
    int rg = threadIdx.x >> 6;   // 0..3
    float s = 0.f, s2 = 0.f;
    for (int v = blockIdx.x * 4 + rg; v < NN; v += BNGRID * 4) {
        float val = g_H[(size_t)v * CH + ch];
        s += val;
        s2 += val * val;
    }
    __shared__ float sh[4][64], sh2[4][64];
    sh[rg][ch] = s; sh2[rg][ch] = s2;
    __syncthreads();
    if (rg == 0) {
        s  = sh[0][ch]  + sh[1][ch]  + sh[2][ch]  + sh[3][ch];
        s2 = sh2[0][ch] + sh2[1][ch] + sh2[2][ch] + sh2[3][ch];
        g_bnp[blockIdx.x * 64 + ch]  = s;
        g_bnp2[blockIdx.x * 64 + ch] = s2;
    }
}

__global__ void k_bnfinal(const float* __restrict__ g, const float* __restrict__ bt) {
    int ch = threadIdx.x;
    if (ch >= CH) return;
    float s = 0.f, s2 = 0.f;
    for (int bidx = 0; bidx < BNGRID; bidx++) {
        s  += g_bnp[bidx * 64 + ch];
        s2 += g_bnp2[bidx * 64 + ch];
    }
    float mu = s / (float)NN;
    float var = s2 / (float)NN - mu * mu;
    float sc = g[ch] * rsqrtf(var + 1e-5f);
    g_scale[ch] = sc;
    g_shift[ch] = bt[ch] - mu * sc;
}

// ---------------- launch ----------------
extern "C" void kernel_launch(void* const* d_in, const int* in_sizes, int n_in,
                              void* d_out, int out_size) {
    const float* x    = (const float*)d_in[0];
    const int*   ei   = (const int*)d_in[1];      // edge_index: int32
    const float* W0   = (const float*)d_in[2];
    const float* U0   = (const float*)d_in[3];
    const float* c0   = (const float*)d_in[4];
    const float* b0   = (const float*)d_in[5];
    const float* g0   = (const float*)d_in[6];
    const float* bt0  = (const float*)d_in[7];
    const float* W1   = (const float*)d_in[8];
    const float* U1   = (const float*)d_in[9];
    const float* c1   = (const float*)d_in[10];
    const float* b1   = (const float*)d_in[11];
    const float* g1   = (const float*)d_in[12];
    const float* bt1  = (const float*)d_in[13];
    const float* W2   = (const float*)d_in[14];
    const float* U2   = (const float*)d_in[15];
    const float* c2   = (const float*)d_in[16];
    const float* b2   = (const float*)d_in[17];
    const int* srcE = ei;
    const int* dstE = ei + NE;
    float* out = (float*)d_out;

    const int GB_E = (NE + 255) / 256;      // 1875
    const int GB_N = SCAN_BLOCKS;           // 118
    const int GB_W = NN / 8;                // 3750 (warp per node, exact)
    const int GB_G = (NN + 127) / 128;      // 235
    const int GB_P = (KZ * CH + 255) / 256; // 64

    // CSR build (graph fixed across layers)
    k_zero_deg<<<GB_N, 256>>>();
    k_count<<<GB_E, 256>>>(dstE);
    k_scan1<<<GB_N, 256>>>();
    k_scan2<<<1, 128>>>();
    k_scan3<<<GB_N, 256>>>();
    k_scatter<<<GB_E, 256>>>(srcE, dstE);

    // ---- layer 0 (input x, no BN folding) ----
    k_L<<<GB_W, 256>>>(x, U0, 0);
    k_attn<<<GB_E, 256>>>(srcE, dstE, c0);
    k_edge<<<GB_W, 256>>>(x, c0, 0);
    k_permW<<<GB_P, 256>>>(W0);
    k_gemm<<<GB_G, 256>>>(b0, nullptr, 1);    // -> g_H (relu'd)
    k_bnstat<<<BNGRID, 256>>>();
    k_bnfinal<<<1, 64>>>(g0, bt0);

    // ---- layer 1 (reads BN0(g_H) on the fly) ----
    k_L<<<GB_W, 256>>>(nullptr, U1, 1);
    k_attn<<<GB_E, 256>>>(srcE, dstE, c1);
    k_edge<<<GB_W, 256>>>(nullptr, c1, 1);
    k_permW<<<GB_P, 256>>>(W1);
    k_gemm<<<GB_G, 256>>>(b1, nullptr, 1);    // -> g_H (relu'd)
    k_bnstat<<<BNGRID, 256>>>();
    k_bnfinal<<<1, 64>>>(g1, bt1);

    // ---- layer 2 (reads BN1(g_H), no relu, writes d_out) ----
    k_L<<<GB_W, 256>>>(nullptr, U2, 1);
    k_attn<<<GB_E, 256>>>(srcE, dstE, c2);
    k_edge<<<GB_W, 256>>>(nullptr, c2, 1);
    k_permW<<<GB_P, 256>>>(W2);
    k_gemm<<<GB_G, 256>>>(b2, out, 0);

    (void)in_sizes; (void)n_in; (void)out_size;
}